// round 11
// baseline (speedup 1.0000x reference)
#include <cuda_runtime.h>

// GNNSurrogate fully fused, r=2 node blocking, swizzled local tile.
// 384 threads/block = 6 samples x 64 threads (12 warps/SM, spill-free:
// reg budget 65536/384 = 170 > ~140 needed; R10's 512-thread config hit the
// 128-reg cap and spilled, eating the occupancy gain).
// - local tile: stride-32 rows, 16B-chunk XOR swizzle (q ^ (row&7)):
//   conflict-free STS.128, broadcast reads unchanged.

#define THREADS 384
#define GROUPS 6
#define BATCH 16384

// shared-memory float offsets
#define ADJ_OFF 0
#define ADJ_SZ  (128 * 129)          // padded stride 129: conflict-free column reads
#define WL_OFF  (ADJ_OFF + ADJ_SZ)
#define BL_OFF  (WL_OFF + 96)
#define W1_OFF  (BL_OFF + 32)
#define B1_OFF  (W1_OFF + 3072)
#define W2_OFF  (B1_OFF + 96)
#define B2_OFF  (W2_OFF + 3072)
#define WRO_OFF (B2_OFF + 96)
#define RED_OFF (WRO_OFF + 32)       // 12 floats (per-warp partials)
#define LOC_OFF (RED_OFF + 16)       // 23024 floats -> 92096 B, 16B aligned
#define SMEM_FLOATS (LOC_OFF + GROUPS * 128 * 32)   // 47600 floats = 190400 B

typedef unsigned long long u64;

__device__ __forceinline__ u64 f2pack(float lo, float hi) {
    u64 r;
    asm("mov.b64 %0, {%1, %2};" : "=l"(r) : "f"(lo), "f"(hi));
    return r;
}
__device__ __forceinline__ void f2unpack(u64 v, float& lo, float& hi) {
    asm("mov.b64 {%0, %1}, %2;" : "=f"(lo), "=f"(hi) : "l"(v));
}
__device__ __forceinline__ u64 ffma2(u64 a, u64 b, u64 c) {
    u64 d;
    asm("fma.rn.f32x2 %0, %1, %2, %3;" : "=l"(d) : "l"(a), "l"(b), "l"(c));
    return d;
}

// one 32->32 matmul step applied to two rows, weights broadcast from smem
__device__ __forceinline__ void mm2(const float* __restrict__ wbase,
                                    const float* __restrict__ bias,
                                    const float* ha, const float* hb,
                                    u64* ta, u64* tb)
{
    const u64* bp = (const u64*)bias;
    #pragma unroll
    for (int q = 0; q < 16; q++) { ta[q] = bp[q]; tb[q] = bp[q]; }
    const ulonglong2* w = (const ulonglong2*)wbase;
    #pragma unroll 4
    for (int k = 0; k < 32; k++) {
        u64 ak = f2pack(ha[k], ha[k]);
        u64 bk = f2pack(hb[k], hb[k]);
        #pragma unroll
        for (int q = 0; q < 8; q++) {
            ulonglong2 p = w[k * 8 + q];
            ta[2 * q]     = ffma2(ak, p.x, ta[2 * q]);
            ta[2 * q + 1] = ffma2(ak, p.y, ta[2 * q + 1]);
            tb[2 * q]     = ffma2(bk, p.x, tb[2 * q]);
            tb[2 * q + 1] = ffma2(bk, p.y, tb[2 * q + 1]);
        }
    }
}

__global__ void __launch_bounds__(THREADS, 1) gnn_fused_kernel(
    const float* __restrict__ x, const float* __restrict__ adj,
    const float* __restrict__ W_lift, const float* __restrict__ b_lift,
    const float* __restrict__ W1, const float* __restrict__ b1,
    const float* __restrict__ W2, const float* __restrict__ b2,
    const float* __restrict__ W_ro, const float* __restrict__ b_ro,
    float* __restrict__ out)
{
    extern __shared__ float sm[];
    const int tid = threadIdx.x;

    // ---- stage adjacency (padded) + weights ----
    for (int idx = tid; idx < 128 * 128; idx += THREADS)
        sm[ADJ_OFF + (idx >> 7) * 129 + (idx & 127)] = adj[idx];
    for (int idx = tid; idx < 96; idx += THREADS)   sm[WL_OFF + idx] = W_lift[idx];
    if (tid < 32)                                   sm[BL_OFF + tid] = b_lift[tid];
    for (int idx = tid; idx < 3072; idx += THREADS) sm[W1_OFF + idx] = W1[idx];
    for (int idx = tid; idx < 96; idx += THREADS)   sm[B1_OFF + idx] = b1[idx];
    for (int idx = tid; idx < 3072; idx += THREADS) sm[W2_OFF + idx] = W2[idx];
    for (int idx = tid; idx < 96; idx += THREADS)   sm[B2_OFF + idx] = b2[idx];
    if (tid < 32)                                   sm[WRO_OFF + tid] = W_ro[tid];
    __syncthreads();

    const int g  = tid >> 6;          // sample group 0..5
    const int i0 = tid & 63;          // first node row
    const int i1 = i0 + 64;           // second node row
    const int b  = blockIdx.x * GROUPS + g;
    const int bc = (b < BATCH) ? b : (BATCH - 1);   // clamped for loads

    // ---- lift for both rows ----
    float ha[32], hb[32];
    {
        const float* xa = x + ((size_t)bc * 128 + i0) * 3;
        const float* xb = x + ((size_t)bc * 128 + i1) * 3;
        float a0 = xa[0], a1 = xa[1], a2 = xa[2];
        float c0 = xb[0], c1 = xb[1], c2 = xb[2];
        #pragma unroll
        for (int j = 0; j < 32; j++) {
            float w0 = sm[WL_OFF + j], w1v = sm[WL_OFF + 32 + j],
                  w2v = sm[WL_OFF + 64 + j], bl = sm[BL_OFF + j];
            ha[j] = fmaf(a0, w0, fmaf(a1, w1v, fmaf(a2, w2v, bl)));
            hb[j] = fmaf(c0, w0, fmaf(c1, w1v, fmaf(c2, w2v, bl)));
        }
    }

    float* loc = sm + LOC_OFF + g * 4096;
    const int sw = i0 & 7;            // swizzle key (i1 = i0+64 -> same low 3 bits)

    for (int l = 0; l < 3; l++) {
        // ---- matmul1 + relu ----
        u64 ta[16], tb[16];
        mm2(sm + W1_OFF + l * 1024, sm + B1_OFF + l * 32, ha, hb, ta, tb);
        #pragma unroll
        for (int q = 0; q < 16; q++) {
            float lo, hi;
            f2unpack(ta[q], lo, hi);
            ha[2 * q] = fmaxf(lo, 0.f); ha[2 * q + 1] = fmaxf(hi, 0.f);
            f2unpack(tb[q], lo, hi);
            hb[2 * q] = fmaxf(lo, 0.f); hb[2 * q + 1] = fmaxf(hi, 0.f);
        }

        // ---- matmul2 ----
        u64 va[16], vb[16];
        mm2(sm + W2_OFF + l * 1024, sm + B2_OFF + l * 32, ha, hb, va, vb);

        // ---- write local rows (swizzled, conflict-free STS.128) ----
        {
            float* ra = loc + i0 * 32;
            float* rb = loc + i1 * 32;
            #pragma unroll
            for (int q = 0; q < 8; q++) {
                ulonglong2 pa; pa.x = va[2 * q]; pa.y = va[2 * q + 1];
                ulonglong2 pb; pb.x = vb[2 * q]; pb.y = vb[2 * q + 1];
                *(ulonglong2*)(ra + ((q ^ sw) << 2)) = pa;
                *(ulonglong2*)(rb + ((q ^ sw) << 2)) = pb;
            }
        }
        __syncthreads();

        // ---- aggregation: both rows share each local[j] broadcast load ----
        u64 aa[16], ab[16];
        #pragma unroll
        for (int q = 0; q < 16; q++) { aa[q] = 0ULL; ab[q] = 0ULL; }
        const float* arowa = sm + ADJ_OFF + i0 * 129;
        const float* arowb = sm + ADJ_OFF + i1 * 129;
        #pragma unroll 2
        for (int j = 0; j < 128; j++) {
            u64 ca = f2pack(arowa[j], arowa[j]);
            u64 cb = f2pack(arowb[j], arowb[j]);
            const float* Lrow = loc + j * 32;
            const int swj = j & 7;
            #pragma unroll
            for (int q = 0; q < 8; q++) {
                ulonglong2 p = *(const ulonglong2*)(Lrow + ((q ^ swj) << 2));
                aa[2 * q]     = ffma2(ca, p.x, aa[2 * q]);
                aa[2 * q + 1] = ffma2(ca, p.y, aa[2 * q + 1]);
                ab[2 * q]     = ffma2(cb, p.x, ab[2 * q]);
                ab[2 * q + 1] = ffma2(cb, p.y, ab[2 * q + 1]);
            }
        }
        #pragma unroll
        for (int q = 0; q < 16; q++) {
            f2unpack(aa[q], ha[2 * q], ha[2 * q + 1]);
            f2unpack(ab[q], hb[2 * q], hb[2 * q + 1]);
        }
        __syncthreads();   // protect local tile before next layer's writes
    }

    // ---- readout ----
    float s = 0.f;
    #pragma unroll
    for (int c = 0; c < 32; c++) {
        float w = sm[WRO_OFF + c];
        s = fmaf(ha[c], w, s);
        s = fmaf(hb[c], w, s);
    }
    #pragma unroll
    for (int o = 16; o > 0; o >>= 1) s += __shfl_xor_sync(0xffffffffu, s, o);
    const int w = tid >> 5;
    if ((tid & 31) == 0) sm[RED_OFF + w] = s;
    __syncthreads();
    if (i0 == 0 && b < BATCH) {
        float tot = sm[RED_OFF + 2 * g] + sm[RED_OFF + 2 * g + 1];
        out[b] = fmaf(tot, 1.f / 128.f, b_ro[0]);
    }
}

extern "C" void kernel_launch(void* const* d_in, const int* in_sizes, int n_in,
                              void* d_out, int out_size)
{
    const float* x      = (const float*)d_in[0];
    const float* adj    = (const float*)d_in[1];
    const float* W_lift = (const float*)d_in[2];
    const float* b_lift = (const float*)d_in[3];
    const float* W1     = (const float*)d_in[4];
    const float* b1     = (const float*)d_in[5];
    const float* W2     = (const float*)d_in[6];
    const float* b2     = (const float*)d_in[7];
    const float* W_ro   = (const float*)d_in[8];
    const float* b_ro   = (const float*)d_in[9];
    float* out = (float*)d_out;

    const size_t smem_bytes = SMEM_FLOATS * sizeof(float);
    cudaFuncSetAttribute(gnn_fused_kernel,
                         cudaFuncAttributeMaxDynamicSharedMemorySize,
                         (int)smem_bytes);

    const int grid = (BATCH + GROUPS - 1) / GROUPS;   // 2731
    gnn_fused_kernel<<<grid, THREADS, smem_bytes>>>(
        x, adj, W_lift, b_lift, W1, b1, W2, b2, W_ro, b_ro, out);
}

// round 13
// speedup vs baseline: 1.2534x; 1.2534x over previous
#include <cuda_runtime.h>
#include <cuda_bf16.h>
#include <cstdint>

// GNNSurrogate hybrid: MLPs on FFMA2 (at their RF-bank roofline), adjacency
// aggregation on mma.sync bf16 m16n8k16 with 3-pass hi/lo error-compensated
// split (rel err ~1e-5). tcgen05 is unavailable (harness compiles PTX target
// sm_103 without the 'a' suffix), so classic HMMA is the tensor path.
//
// 512 threads = 4 groups x 128 (one sample per group; thread = node row i for
// the scalar phases; warp wg in group owns M-tiles 2wg,2wg+1 for the MMA).
// adj is batch-constant: converted ONCE per block into A-fragment-packed bf16
// hi/lo arrays (LDS.128 per fragment). MLP output is stored directly in
// B-fragment-packed order via 16-bit smem stores. D fragments round-trip via a
// swizzled h-tile (buffer shared with the B arrays) back to per-thread h.

#define THREADS 512
#define NGROUPS 4
#define BATCH 16384

// shared-memory offsets in 4-byte units
#define WL_OFF   0
#define BL_OFF   96
#define W1_OFF   128
#define B1_OFF   3200
#define W2_OFF   3296
#define B2_OFF   6368
#define WRO_OFF  6464
#define RED_OFF  6496          // 16 per-warp partials
#define AFH_OFF  6528          // adj A-frag hi: 8mt*8kc*32*4 u32 = 8192
#define AFL_OFF  (AFH_OFF + 8192)
#define LB_OFF   (AFL_OFF + 8192)   // per group 4096 u32: [Bhi 2048][Blo 2048] == htile 4096 f32
#define SMEM_FLOATS (LB_OFF + NGROUPS * 4096)   // 39296 -> 157184 B

typedef unsigned long long u64;
typedef unsigned short u16;

__device__ __forceinline__ u64 f2pack(float lo, float hi) {
    u64 r; asm("mov.b64 %0, {%1, %2};" : "=l"(r) : "f"(lo), "f"(hi)); return r;
}
__device__ __forceinline__ void f2unpack(u64 v, float& lo, float& hi) {
    asm("mov.b64 {%0, %1}, %2;" : "=f"(lo), "=f"(hi) : "l"(v));
}
__device__ __forceinline__ u64 ffma2(u64 a, u64 b, u64 c) {
    u64 d; asm("fma.rn.f32x2 %0, %1, %2, %3;" : "=l"(d) : "l"(a), "l"(b), "l"(c));
    return d;
}

__device__ __forceinline__ u16 bfbits(float f) {
    __nv_bfloat16 b = __float2bfloat16_rn(f);
    return *reinterpret_cast<u16*>(&b);
}
__device__ __forceinline__ float bfval(u16 u) {
    __nv_bfloat16 b = *reinterpret_cast<__nv_bfloat16*>(&u);
    return __bfloat162float(b);
}
// split f into bf16 hi + bf16 lo (f ~= hi + lo)
__device__ __forceinline__ void bfsplit(float f, u16& h, u16& l) {
    h = bfbits(f);
    l = bfbits(f - bfval(h));
}

__device__ __forceinline__ void mma_bf16(float* d, const uint32_t* a, const uint32_t* b) {
    asm volatile(
        "mma.sync.aligned.m16n8k16.row.col.f32.bf16.bf16.f32 "
        "{%0,%1,%2,%3}, {%4,%5,%6,%7}, {%8,%9}, {%0,%1,%2,%3};"
        : "+f"(d[0]), "+f"(d[1]), "+f"(d[2]), "+f"(d[3])
        : "r"(a[0]), "r"(a[1]), "r"(a[2]), "r"(a[3]), "r"(b[0]), "r"(b[1]));
}

// one 32->32 FFMA2 matmul for a single row, weights broadcast from smem
__device__ __forceinline__ void mm1(const float* __restrict__ wbase,
                                    const float* __restrict__ bias,
                                    const float* h, u64* t2)
{
    const u64* bp = (const u64*)bias;
    #pragma unroll
    for (int q = 0; q < 16; q++) t2[q] = bp[q];
    const ulonglong2* w = (const ulonglong2*)wbase;
    #pragma unroll 4
    for (int k = 0; k < 32; k++) {
        u64 hk = f2pack(h[k], h[k]);
        #pragma unroll
        for (int q = 0; q < 8; q++) {
            ulonglong2 p = w[k * 8 + q];
            t2[2 * q]     = ffma2(hk, p.x, t2[2 * q]);
            t2[2 * q + 1] = ffma2(hk, p.y, t2[2 * q + 1]);
        }
    }
}

__global__ void __launch_bounds__(THREADS, 1) gnn_mma_kernel(
    const float* __restrict__ x, const float* __restrict__ adj,
    const float* __restrict__ W_lift, const float* __restrict__ b_lift,
    const float* __restrict__ W1, const float* __restrict__ b1,
    const float* __restrict__ W2, const float* __restrict__ b2,
    const float* __restrict__ W_ro, const float* __restrict__ b_ro,
    float* __restrict__ out)
{
    extern __shared__ float sm[];
    char* smc = (char*)sm;
    const int tid  = threadIdx.x;
    const int wid  = tid >> 5;
    const int lane = tid & 31;
    const int g    = tid >> 7;         // sample group 0..3
    const int wg   = (tid >> 5) & 3;   // warp in group 0..3
    const int i    = tid & 127;        // node row
    const int b    = blockIdx.x * NGROUPS + g;

    // ---- stage weights ----
    for (int idx = tid; idx < 96; idx += THREADS)   sm[WL_OFF + idx] = W_lift[idx];
    if (tid < 32)                                   sm[BL_OFF + tid] = b_lift[tid];
    for (int idx = tid; idx < 3072; idx += THREADS) sm[W1_OFF + idx] = W1[idx];
    for (int idx = tid; idx < 96; idx += THREADS)   sm[B1_OFF + idx] = b1[idx];
    for (int idx = tid; idx < 3072; idx += THREADS) sm[W2_OFF + idx] = W2[idx];
    for (int idx = tid; idx < 96; idx += THREADS)   sm[B2_OFF + idx] = b2[idx];
    if (tid < 32)                                   sm[WRO_OFF + tid] = W_ro[tid];

    // ---- stage adj in A-fragment-packed bf16 hi/lo order ----
    // slot s = (mt*8 + kc)*32 + ln ; regs: a0[r][k,k+1] a1[r+8] a2[r][k+8] a3[r+8][k+8]
    for (int s = tid; s < 2048; s += THREADS) {
        int mt = s >> 8, kc = (s >> 5) & 7, ln = s & 31;
        int r = mt * 16 + (ln >> 2);
        int k = kc * 16 + (ln & 3) * 2;
        const float* a0 = adj + r * 128 + k;
        const float* a1 = a0 + 8 * 128;
        uint32_t hi[4], lo[4];
        #pragma unroll
        for (int e = 0; e < 4; e++) {
            const float* p = (e & 1) ? a1 : a0;     // a0,a1,a2,a3
            int kk = (e >> 1) * 8;
            u16 h0, l0, h1, l1;
            bfsplit(p[kk], h0, l0);
            bfsplit(p[kk + 1], h1, l1);
            hi[e] = (uint32_t)h0 | ((uint32_t)h1 << 16);
            lo[e] = (uint32_t)l0 | ((uint32_t)l1 << 16);
        }
        *(uint4*)(smc + (AFH_OFF + s * 4) * 4) = make_uint4(hi[0], hi[1], hi[2], hi[3]);
        *(uint4*)(smc + (AFL_OFF + s * 4) * 4) = make_uint4(lo[0], lo[1], lo[2], lo[3]);
    }
    __syncthreads();

    // ---- lift: h = x @ W_lift + b_lift (per-thread, thread = node i) ----
    float h[32];
    {
        const float* xp = x + ((size_t)b * 128 + i) * 3;
        float x0 = xp[0], x1 = xp[1], x2 = xp[2];
        #pragma unroll
        for (int j = 0; j < 32; j++)
            h[j] = fmaf(x0, sm[WL_OFF + j],
                   fmaf(x1, sm[WL_OFF + 32 + j],
                   fmaf(x2, sm[WL_OFF + 64 + j], sm[BL_OFF + j])));
    }

    char* lb = smc + (LB_OFF + g * 4096) * 4;       // group buffer: Bhi[8KB] Blo[8KB] == htile
    // localB write constants for this thread (k = i):
    // byte = (n>>3)*2048 + (n&7)*32 + kc*256 + sub*8 + reg*4 + half*2
    const int wr_c = ((i >> 4) << 8) + (((i >> 1) & 3) << 3) + (((i >> 3) & 1) << 2) + ((i & 1) << 1);

    for (int l = 0; l < 3; l++) {
        // ---- MLP1 + relu ----
        u64 t2[16];
        mm1(sm + W1_OFF + l * 1024, sm + B1_OFF + l * 32, h, t2);
        #pragma unroll
        for (int q = 0; q < 16; q++) {
            float lo, hi;
            f2unpack(t2[q], lo, hi);
            h[2 * q]     = fmaxf(lo, 0.f);
            h[2 * q + 1] = fmaxf(hi, 0.f);
        }
        // ---- MLP2 -> v, write bf16 hi/lo into B-fragment-packed arrays ----
        u64 v2[16];
        mm1(sm + W2_OFF + l * 1024, sm + B2_OFF + l * 32, h, v2);
        #pragma unroll
        for (int q = 0; q < 16; q++) {
            float vlo, vhi;
            f2unpack(v2[q], vlo, vhi);
            #pragma unroll
            for (int s = 0; s < 2; s++) {
                int n = 2 * q + s;
                float v = s ? vhi : vlo;
                u16 bh, bl;
                bfsplit(v, bh, bl);
                int off = ((n >> 3) << 11) + ((n & 7) << 5) + wr_c;
                *(u16*)(lb + off)        = bh;
                *(u16*)(lb + 8192 + off) = bl;
            }
        }
        __syncthreads();

        // ---- aggregation MMA: D = Ahi@Bhi + Alo@Bhi + Ahi@Blo ----
        float d[32];
        #pragma unroll
        for (int q = 0; q < 32; q++) d[q] = 0.f;
        #pragma unroll 1
        for (int kc = 0; kc < 8; kc++) {
            uint2 bh[4], blo[4];
            #pragma unroll
            for (int nt = 0; nt < 4; nt++)
                bh[nt] = *(const uint2*)(lb + (((nt * 8 + kc) * 32 + lane) << 3));
            uint4 ah[2], al[2];
            #pragma unroll
            for (int mt = 0; mt < 2; mt++) {
                int sidx = (((2 * wg + mt) * 8 + kc) * 32 + lane) << 4;
                ah[mt] = *(const uint4*)(smc + AFH_OFF * 4 + sidx);
                al[mt] = *(const uint4*)(smc + AFL_OFF * 4 + sidx);
            }
            #pragma unroll
            for (int mt = 0; mt < 2; mt++)
                #pragma unroll
                for (int nt = 0; nt < 4; nt++) {
                    float* dd = d + ((mt * 4 + nt) << 2);
                    mma_bf16(dd, (const uint32_t*)&ah[mt], (const uint32_t*)&bh[nt]);
                    mma_bf16(dd, (const uint32_t*)&al[mt], (const uint32_t*)&bh[nt]);
                }
            #pragma unroll
            for (int nt = 0; nt < 4; nt++)
                blo[nt] = *(const uint2*)(lb + 8192 + (((nt * 8 + kc) * 32 + lane) << 3));
            #pragma unroll
            for (int mt = 0; mt < 2; mt++)
                #pragma unroll
                for (int nt = 0; nt < 4; nt++)
                    mma_bf16(d + ((mt * 4 + nt) << 2),
                             (const uint32_t*)&ah[mt], (const uint32_t*)&blo[nt]);
        }
        __syncthreads();   // all reads of lb done before htile overwrites it

        // ---- D fragments -> swizzled h-tile (over lb) ----
        #pragma unroll
        for (int mt = 0; mt < 2; mt++) {
            int r0 = 32 * wg + 16 * mt + (lane >> 2);
            #pragma unroll
            for (int nt = 0; nt < 4; nt++) {
                int c = nt * 8 + (lane & 3) * 2;
                const float* dd = d + ((mt * 4 + nt) << 2);
                int ch = c >> 2, cb = (c & 3) * 4;
                *(float2*)(lb + r0 * 128 + (((ch ^ (r0 & 7)) << 4) + cb))
                    = make_float2(dd[0], dd[1]);
                int r1 = r0 + 8;
                *(float2*)(lb + r1 * 128 + (((ch ^ (r1 & 7)) << 4) + cb))
                    = make_float2(dd[2], dd[3]);
            }
        }
        __syncthreads();

        // ---- h-tile -> per-thread h ----
        #pragma unroll
        for (int q = 0; q < 8; q++) {
            float4 p = *(const float4*)(lb + i * 128 + (((q ^ (i & 7)) << 4)));
            h[4 * q] = p.x; h[4 * q + 1] = p.y; h[4 * q + 2] = p.z; h[4 * q + 3] = p.w;
        }
        __syncthreads();   // htile reads done before next layer writes lb
    }

    // ---- readout ----
    float s = 0.f;
    #pragma unroll
    for (int c = 0; c < 32; c++) s = fmaf(h[c], sm[WRO_OFF + c], s);
    #pragma unroll
    for (int o = 16; o > 0; o >>= 1) s += __shfl_xor_sync(0xffffffffu, s, o);
    if (lane == 0) sm[RED_OFF + wid] = s;
    __syncthreads();
    if (i == 0) {
        float tot = sm[RED_OFF + 4 * g] + sm[RED_OFF + 4 * g + 1] +
                    sm[RED_OFF + 4 * g + 2] + sm[RED_OFF + 4 * g + 3];
        out[b] = fmaf(tot, 1.f / 128.f, b_ro[0]);
    }
}

extern "C" void kernel_launch(void* const* d_in, const int* in_sizes, int n_in,
                              void* d_out, int out_size)
{
    const float* x      = (const float*)d_in[0];
    const float* adj    = (const float*)d_in[1];
    const float* W_lift = (const float*)d_in[2];
    const float* b_lift = (const float*)d_in[3];
    const float* W1     = (const float*)d_in[4];
    const float* b1     = (const float*)d_in[5];
    const float* W2     = (const float*)d_in[6];
    const float* b2     = (const float*)d_in[7];
    const float* W_ro   = (const float*)d_in[8];
    const float* b_ro   = (const float*)d_in[9];
    float* out = (float*)d_out;

    const size_t smem_bytes = SMEM_FLOATS * sizeof(float);
    cudaFuncSetAttribute(gnn_mma_kernel,
                         cudaFuncAttributeMaxDynamicSharedMemorySize,
                         (int)smem_bytes);

    gnn_mma_kernel<<<BATCH / NGROUPS, THREADS, smem_bytes>>>(
        x, adj, W_lift, b_lift, W1, b1, W2, b2, W_ro, b_ro, out);
}

// round 15
// speedup vs baseline: 1.7049x; 1.3602x over previous
#include <cuda_runtime.h>
#include <cuda_bf16.h>
#include <cstdint>

// GNNSurrogate: ALL GEMMs (MLP1, MLP2, aggregation) on mma.sync bf16 m16n8k16
// with 3-pass hi/lo error compensation. Chain stays in registers:
// D-fragments of one GEMM repack (register-only) into A-fragments of the next;
// only the MLP2->agg transpose goes through SMEM (B-fragment-packed scatter).
// R15 fix: weight B-frag sections packed at stride 4096B (hi +0, lo +2048) --
// R14 used stride 8192B and overran into the adj fragment arrays (rel_err 0.35).
// 512 threads = 4 groups x 4 warps; warp owns 32 node rows of its sample.

#define THREADS 512
#define NGROUPS 4
#define BATCH 16384

// shared-memory float offsets
#define WL_OFF  0        // 96  (W_lift [3][32])
#define BL_OFF  96       // 32
#define B1_OFF  128      // 96  (b1 [3][32])
#define B2_OFF  224      // 96
#define WRO_OFF 320      // 32
#define RED_OFF 352      // 16 per-warp partials
#define WB_OFF  384      // 6144 floats: 6 (l,w) sections x 4096B [hi 2048 | lo 2048]
#define AFH_OFF 6528     // 8192: adj A-frag hi (8mt*8kc*32 lanes * uint4)
#define AFL_OFF 14720    // 8192: adj A-frag lo
#define LB_OFF  22912    // + g*4096: v B-packed [hi 8KB][lo 8KB]
#define SMEM_FLOATS (LB_OFF + NGROUPS * 4096)   // 39296 -> 157184 B

typedef unsigned short u16;

__device__ __forceinline__ u16 bfh(float f) {
    u16 r; asm("cvt.rn.bf16.f32 %0, %1;" : "=h"(r) : "f"(f)); return r;
}
__device__ __forceinline__ float bfup(u16 h) {
    return __uint_as_float(((uint32_t)h) << 16);
}
// split pair (f0,f1) into packed bf16x2 hi and lo
__device__ __forceinline__ void split2(float f0, float f1, uint32_t& hi, uint32_t& lo) {
    u16 h0 = bfh(f0), h1 = bfh(f1);
    u16 l0 = bfh(f0 - bfup(h0)), l1 = bfh(f1 - bfup(h1));
    hi = (uint32_t)h0 | ((uint32_t)h1 << 16);
    lo = (uint32_t)l0 | ((uint32_t)l1 << 16);
}

__device__ __forceinline__ void mma_bf16(float* d, const uint32_t* a, const uint32_t* b) {
    asm volatile(
        "mma.sync.aligned.m16n8k16.row.col.f32.bf16.bf16.f32 "
        "{%0,%1,%2,%3}, {%4,%5,%6,%7}, {%8,%9}, {%0,%1,%2,%3};"
        : "+f"(d[0]), "+f"(d[1]), "+f"(d[2]), "+f"(d[3])
        : "r"(a[0]), "r"(a[1]), "r"(a[2]), "r"(a[3]), "r"(b[0]), "r"(b[1]));
}

// h (32 floats, D layout [mt][nt][4]) -> MLP: h@W + bias (relu optional). In place.
__device__ __forceinline__ void mlp_step(float* h, const char* wsec,
                                         const float* bias, int lane, bool relu)
{
    // D -> A fragment repack (register-only) with hi/lo split
    uint32_t ah[2][2][4], al[2][2][4];
    #pragma unroll
    for (int mt = 0; mt < 2; mt++)
        #pragma unroll
        for (int kc = 0; kc < 2; kc++) {
            const float* d0 = h + (mt * 4 + 2 * kc) * 4;
            const float* d1 = h + (mt * 4 + 2 * kc + 1) * 4;
            split2(d0[0], d0[1], ah[mt][kc][0], al[mt][kc][0]);
            split2(d0[2], d0[3], ah[mt][kc][1], al[mt][kc][1]);
            split2(d1[0], d1[1], ah[mt][kc][2], al[mt][kc][2]);
            split2(d1[2], d1[3], ah[mt][kc][3], al[mt][kc][3]);
        }
    float d[32];
    const int q2 = (lane & 3) * 2;
    #pragma unroll
    for (int nt = 0; nt < 4; nt++) {
        float2 bb = *(const float2*)(bias + nt * 8 + q2);
        #pragma unroll
        for (int mt = 0; mt < 2; mt++) {
            float* dd = d + (mt * 4 + nt) * 4;
            dd[0] = bb.x; dd[1] = bb.y; dd[2] = bb.x; dd[3] = bb.y;
        }
    }
    #pragma unroll
    for (int kc = 0; kc < 2; kc++) {
        uint2 wh[4], wl[4];
        #pragma unroll
        for (int nt = 0; nt < 4; nt++) {
            const char* p = wsec + ((nt * 2 + kc) * 32 + lane) * 8;
            wh[nt] = *(const uint2*)p;
            wl[nt] = *(const uint2*)(p + 2048);
        }
        #pragma unroll
        for (int mt = 0; mt < 2; mt++)
            #pragma unroll
            for (int nt = 0; nt < 4; nt++) {
                float* dd = d + (mt * 4 + nt) * 4;
                mma_bf16(dd, ah[mt][kc], (const uint32_t*)&wh[nt]);
                mma_bf16(dd, al[mt][kc], (const uint32_t*)&wh[nt]);
                mma_bf16(dd, ah[mt][kc], (const uint32_t*)&wl[nt]);
            }
    }
    #pragma unroll
    for (int e = 0; e < 32; e++) h[e] = relu ? fmaxf(d[e], 0.f) : d[e];
}

__global__ void __launch_bounds__(THREADS, 1) gnn_mma2_kernel(
    const float* __restrict__ x, const float* __restrict__ adj,
    const float* __restrict__ W_lift, const float* __restrict__ b_lift,
    const float* __restrict__ W1, const float* __restrict__ b1,
    const float* __restrict__ W2, const float* __restrict__ b2,
    const float* __restrict__ W_ro, const float* __restrict__ b_ro,
    float* __restrict__ out)
{
    extern __shared__ float sm[];
    char* smc = (char*)sm;
    const int tid  = threadIdx.x;
    const int wid  = tid >> 5;
    const int lane = tid & 31;
    const int g    = tid >> 7;         // sample group 0..3
    const int wg   = (tid >> 5) & 3;   // warp in group (owns rows 32wg..32wg+31)
    const int b    = blockIdx.x * NGROUPS + g;
    const int q2   = (lane & 3) * 2;
    const int rq   = lane >> 2;

    // ---- small weights to smem ----
    for (int idx = tid; idx < 96; idx += THREADS) sm[WL_OFF + idx] = W_lift[idx];
    if (tid < 32)                                 sm[BL_OFF + tid] = b_lift[tid];
    for (int idx = tid; idx < 96; idx += THREADS) sm[B1_OFF + idx] = b1[idx];
    for (int idx = tid; idx < 96; idx += THREADS) sm[B2_OFF + idx] = b2[idx];
    if (tid < 32)                                 sm[WRO_OFF + tid] = W_ro[tid];

    // ---- stage W1/W2 as B-fragment-packed bf16 hi/lo (6 sections x 4096B) ----
    for (int s = tid; s < 1536; s += THREADS) {
        int ln = s & 31, kc = (s >> 5) & 1, nt = (s >> 6) & 3, w = (s >> 8) & 1, l = s >> 9;
        const float* W = (w ? W2 : W1) + l * 1024;
        int n = nt * 8 + (ln >> 2), k0 = kc * 16 + (ln & 3) * 2;
        uint32_t hi0, lo0, hi1, lo1;
        split2(W[k0 * 32 + n],        W[(k0 + 1) * 32 + n], hi0, lo0);
        split2(W[(k0 + 8) * 32 + n],  W[(k0 + 9) * 32 + n], hi1, lo1);
        char* base = smc + WB_OFF * 4 + (l * 2 + w) * 4096 + ((nt * 2 + kc) * 32 + ln) * 8;
        *(uint2*)base          = make_uint2(hi0, hi1);
        *(uint2*)(base + 2048) = make_uint2(lo0, lo1);
    }

    // ---- stage adj as A-fragment-packed bf16 hi/lo ----
    for (int s = tid; s < 2048; s += THREADS) {
        int mt = s >> 8, kc = (s >> 5) & 7, ln = s & 31;
        int r = mt * 16 + (ln >> 2);
        int k = kc * 16 + (ln & 3) * 2;
        const float* a0 = adj + r * 128 + k;
        const float* a1 = a0 + 8 * 128;
        uint32_t hi[4], lo[4];
        split2(a0[0], a0[1], hi[0], lo[0]);
        split2(a1[0], a1[1], hi[1], lo[1]);
        split2(a0[8], a0[9], hi[2], lo[2]);
        split2(a1[8], a1[9], hi[3], lo[3]);
        *(uint4*)(smc + (AFH_OFF + s * 4) * 4) = make_uint4(hi[0], hi[1], hi[2], hi[3]);
        *(uint4*)(smc + (AFL_OFF + s * 4) * 4) = make_uint4(lo[0], lo[1], lo[2], lo[3]);
    }
    __syncthreads();

    // ---- lift directly into D-layout regs: rows 32wg+16mt+8rh+rq ----
    float h[32];
    {
        float xr[4][3];
        #pragma unroll
        for (int mt = 0; mt < 2; mt++)
            #pragma unroll
            for (int rh = 0; rh < 2; rh++) {
                int row = 32 * wg + 16 * mt + 8 * rh + rq;
                const float* xp = x + ((size_t)b * 128 + row) * 3;
                xr[mt * 2 + rh][0] = xp[0];
                xr[mt * 2 + rh][1] = xp[1];
                xr[mt * 2 + rh][2] = xp[2];
            }
        #pragma unroll
        for (int nt = 0; nt < 4; nt++) {
            int c0 = nt * 8 + q2;
            float2 w0 = *(const float2*)(sm + WL_OFF + c0);
            float2 w1 = *(const float2*)(sm + WL_OFF + 32 + c0);
            float2 w2 = *(const float2*)(sm + WL_OFF + 64 + c0);
            float2 bb = *(const float2*)(sm + BL_OFF + c0);
            #pragma unroll
            for (int mt = 0; mt < 2; mt++)
                #pragma unroll
                for (int rh = 0; rh < 2; rh++) {
                    const float* xv = xr[mt * 2 + rh];
                    int idx = (mt * 4 + nt) * 4 + rh * 2;
                    h[idx]     = fmaf(xv[0], w0.x, fmaf(xv[1], w1.x, fmaf(xv[2], w2.x, bb.x)));
                    h[idx + 1] = fmaf(xv[0], w0.y, fmaf(xv[1], w1.y, fmaf(xv[2], w2.y, bb.y)));
                }
        }
    }

    char* lb = smc + (LB_OFF + g * 4096) * 4;     // [Bhi 8KB][Blo 8KB]

    for (int l = 0; l < 3; l++) {
        // ---- MLP1 (+relu) and MLP2, all register-resident ----
        mlp_step(h, smc + WB_OFF * 4 + (l * 2 + 0) * 4096, sm + B1_OFF + l * 32, lane, true);
        mlp_step(h, smc + WB_OFF * 4 + (l * 2 + 1) * 4096, sm + B2_OFF + l * 32, lane, false);

        // ---- scatter v into agg B-fragment-packed hi/lo arrays ----
        #pragma unroll
        for (int mt = 0; mt < 2; mt++)
            #pragma unroll
            for (int rh = 0; rh < 2; rh++) {
                int j = 32 * wg + 16 * mt + 8 * rh + rq;
                int joff = ((j >> 4) << 8) | (((j >> 1) & 3) << 3) |
                           (((j >> 3) & 1) << 2) | ((j & 1) << 1);
                #pragma unroll
                for (int nt = 0; nt < 4; nt++) {
                    int idx = (mt * 4 + nt) * 4 + rh * 2;
                    u16 h0 = bfh(h[idx]);
                    u16 l0 = bfh(h[idx] - bfup(h0));
                    u16 h1 = bfh(h[idx + 1]);
                    u16 l1 = bfh(h[idx + 1] - bfup(h1));
                    int off0 = (nt << 11) | (q2 << 5) | joff;
                    int off1 = (nt << 11) | ((q2 + 1) << 5) | joff;
                    *(u16*)(lb + off0)        = h0;
                    *(u16*)(lb + 8192 + off0) = l0;
                    *(u16*)(lb + off1)        = h1;
                    *(u16*)(lb + 8192 + off1) = l1;
                }
            }
        __syncthreads();

        // ---- aggregation: D = Ahi@Bhi + Alo@Bhi + Ahi@Blo ----
        float d[32];
        #pragma unroll
        for (int e = 0; e < 32; e++) d[e] = 0.f;
        #pragma unroll 1
        for (int kc = 0; kc < 8; kc++) {
            uint2 bh[4];
            #pragma unroll
            for (int nt = 0; nt < 4; nt++)
                bh[nt] = *(const uint2*)(lb + (((nt * 8 + kc) * 32 + lane) << 3));
            uint4 ahh[2], all[2];
            #pragma unroll
            for (int mt = 0; mt < 2; mt++) {
                int sidx = ((((2 * wg + mt) * 8 + kc) * 32 + lane) << 4);
                ahh[mt] = *(const uint4*)(smc + AFH_OFF * 4 + sidx);
                all[mt] = *(const uint4*)(smc + AFL_OFF * 4 + sidx);
            }
            #pragma unroll
            for (int mt = 0; mt < 2; mt++)
                #pragma unroll
                for (int nt = 0; nt < 4; nt++) {
                    float* dd = d + ((mt * 4 + nt) << 2);
                    mma_bf16(dd, (const uint32_t*)&ahh[mt], (const uint32_t*)&bh[nt]);
                    mma_bf16(dd, (const uint32_t*)&all[mt], (const uint32_t*)&bh[nt]);
                }
            uint2 bl[4];
            #pragma unroll
            for (int nt = 0; nt < 4; nt++)
                bl[nt] = *(const uint2*)(lb + 8192 + (((nt * 8 + kc) * 32 + lane) << 3));
            #pragma unroll
            for (int mt = 0; mt < 2; mt++)
                #pragma unroll
                for (int nt = 0; nt < 4; nt++)
                    mma_bf16(d + ((mt * 4 + nt) << 2),
                             (const uint32_t*)&ahh[mt], (const uint32_t*)&bl[nt]);
        }
        #pragma unroll
        for (int e = 0; e < 32; e++) h[e] = d[e];
        __syncthreads();   // lb reads done before next layer's scatter
    }

    // ---- readout from D-layout regs ----
    float s = 0.f;
    #pragma unroll
    for (int nt = 0; nt < 4; nt++) {
        int c0 = nt * 8 + q2;
        float2 w = *(const float2*)(sm + WRO_OFF + c0);
        #pragma unroll
        for (int mt = 0; mt < 2; mt++) {
            const float* dd = h + (mt * 4 + nt) * 4;
            s = fmaf(dd[0] + dd[2], w.x, s);
            s = fmaf(dd[1] + dd[3], w.y, s);
        }
    }
    #pragma unroll
    for (int o = 16; o > 0; o >>= 1) s += __shfl_xor_sync(0xffffffffu, s, o);
    if (lane == 0) sm[RED_OFF + wid] = s;
    __syncthreads();
    if ((tid & 127) == 0) {
        float tot = sm[RED_OFF + 4 * g] + sm[RED_OFF + 4 * g + 1] +
                    sm[RED_OFF + 4 * g + 2] + sm[RED_OFF + 4 * g + 3];
        out[b] = fmaf(tot, 1.f / 128.f, b_ro[0]);
    }
}

extern "C" void kernel_launch(void* const* d_in, const int* in_sizes, int n_in,
                              void* d_out, int out_size)
{
    const float* x      = (const float*)d_in[0];
    const float* adj    = (const float*)d_in[1];
    const float* W_lift = (const float*)d_in[2];
    const float* b_lift = (const float*)d_in[3];
    const float* W1     = (const float*)d_in[4];
    const float* b1     = (const float*)d_in[5];
    const float* W2     = (const float*)d_in[6];
    const float* b2     = (const float*)d_in[7];
    const float* W_ro   = (const float*)d_in[8];
    const float* b_ro   = (const float*)d_in[9];
    float* out = (float*)d_out;

    const size_t smem_bytes = SMEM_FLOATS * sizeof(float);
    cudaFuncSetAttribute(gnn_mma2_kernel,
                         cudaFuncAttributeMaxDynamicSharedMemorySize,
                         (int)smem_bytes);

    gnn_mma2_kernel<<<BATCH / NGROUPS, THREADS, smem_bytes>>>(
        x, adj, W_lift, b_lift, W1, b1, W2, b2, W_ro, b_ro, out);
}

// round 16
// speedup vs baseline: 2.7394x; 1.6068x over previous
#include <cuda_runtime.h>
#include <cuda_bf16.h>
#include <cstdint>

// GNNSurrogate: ALL GEMMs (MLP1, MLP2, aggregation) on mma.sync bf16 m16n8k16
// with 3-pass hi/lo error compensation; register-resident chain (D-frags repack
// to A-frags), only the MLP2->agg transpose goes through SMEM.
// R16: double-buffered scatter tile -> ONE block sync per layer (was 2), and
// agg kc-loop unrolled x2 so fragment loads overlap the previous chunk's MMAs.
// 512 threads = 4 groups x 4 warps; warp owns 32 node rows of its sample.

#define THREADS 512
#define NGROUPS 4
#define BATCH 16384

// shared-memory float offsets
#define WL_OFF  0        // 96  (W_lift [3][32])
#define BL_OFF  96       // 32
#define B1_OFF  128      // 96  (b1 [3][32])
#define B2_OFF  224      // 96
#define WRO_OFF 320      // 32
#define RED_OFF 352      // 16 per-warp partials
#define WB_OFF  384      // 6144 floats: 6 (l,w) sections x 4096B [hi 2048 | lo 2048]
#define AFH_OFF 6528     // 8192: adj A-frag hi (8mt*8kc*32 lanes * uint4)
#define AFL_OFF 14720    // 8192: adj A-frag lo
#define LB_OFF  22912    // + g*8192: v B-packed, DOUBLE buffered: 2 x [hi 8KB][lo 8KB]
#define SMEM_FLOATS (LB_OFF + NGROUPS * 8192)   // 55680 -> 222720 B

typedef unsigned short u16;

__device__ __forceinline__ u16 bfh(float f) {
    u16 r; asm("cvt.rn.bf16.f32 %0, %1;" : "=h"(r) : "f"(f)); return r;
}
__device__ __forceinline__ float bfup(u16 h) {
    return __uint_as_float(((uint32_t)h) << 16);
}
// split pair (f0,f1) into packed bf16x2 hi and lo
__device__ __forceinline__ void split2(float f0, float f1, uint32_t& hi, uint32_t& lo) {
    u16 h0 = bfh(f0), h1 = bfh(f1);
    u16 l0 = bfh(f0 - bfup(h0)), l1 = bfh(f1 - bfup(h1));
    hi = (uint32_t)h0 | ((uint32_t)h1 << 16);
    lo = (uint32_t)l0 | ((uint32_t)l1 << 16);
}

__device__ __forceinline__ void mma_bf16(float* d, const uint32_t* a, const uint32_t* b) {
    asm volatile(
        "mma.sync.aligned.m16n8k16.row.col.f32.bf16.bf16.f32 "
        "{%0,%1,%2,%3}, {%4,%5,%6,%7}, {%8,%9}, {%0,%1,%2,%3};"
        : "+f"(d[0]), "+f"(d[1]), "+f"(d[2]), "+f"(d[3])
        : "r"(a[0]), "r"(a[1]), "r"(a[2]), "r"(a[3]), "r"(b[0]), "r"(b[1]));
}

// h (32 floats, D layout [mt][nt][4]) -> MLP: h@W + bias (relu optional). In place.
__device__ __forceinline__ void mlp_step(float* h, const char* wsec,
                                         const float* bias, int lane, bool relu)
{
    // D -> A fragment repack (register-only) with hi/lo split
    uint32_t ah[2][2][4], al[2][2][4];
    #pragma unroll
    for (int mt = 0; mt < 2; mt++)
        #pragma unroll
        for (int kc = 0; kc < 2; kc++) {
            const float* d0 = h + (mt * 4 + 2 * kc) * 4;
            const float* d1 = h + (mt * 4 + 2 * kc + 1) * 4;
            split2(d0[0], d0[1], ah[mt][kc][0], al[mt][kc][0]);
            split2(d0[2], d0[3], ah[mt][kc][1], al[mt][kc][1]);
            split2(d1[0], d1[1], ah[mt][kc][2], al[mt][kc][2]);
            split2(d1[2], d1[3], ah[mt][kc][3], al[mt][kc][3]);
        }
    float d[32];
    const int q2 = (lane & 3) * 2;
    #pragma unroll
    for (int nt = 0; nt < 4; nt++) {
        float2 bb = *(const float2*)(bias + nt * 8 + q2);
        #pragma unroll
        for (int mt = 0; mt < 2; mt++) {
            float* dd = d + (mt * 4 + nt) * 4;
            dd[0] = bb.x; dd[1] = bb.y; dd[2] = bb.x; dd[3] = bb.y;
        }
    }
    #pragma unroll
    for (int kc = 0; kc < 2; kc++) {
        uint2 wh[4], wl[4];
        #pragma unroll
        for (int nt = 0; nt < 4; nt++) {
            const char* p = wsec + ((nt * 2 + kc) * 32 + lane) * 8;
            wh[nt] = *(const uint2*)p;
            wl[nt] = *(const uint2*)(p + 2048);
        }
        #pragma unroll
        for (int mt = 0; mt < 2; mt++)
            #pragma unroll
            for (int nt = 0; nt < 4; nt++) {
                float* dd = d + (mt * 4 + nt) * 4;
                mma_bf16(dd, ah[mt][kc], (const uint32_t*)&wh[nt]);
                mma_bf16(dd, al[mt][kc], (const uint32_t*)&wh[nt]);
                mma_bf16(dd, ah[mt][kc], (const uint32_t*)&wl[nt]);
            }
    }
    #pragma unroll
    for (int e = 0; e < 32; e++) h[e] = relu ? fmaxf(d[e], 0.f) : d[e];
}

__global__ void __launch_bounds__(THREADS, 1) gnn_mma3_kernel(
    const float* __restrict__ x, const float* __restrict__ adj,
    const float* __restrict__ W_lift, const float* __restrict__ b_lift,
    const float* __restrict__ W1, const float* __restrict__ b1,
    const float* __restrict__ W2, const float* __restrict__ b2,
    const float* __restrict__ W_ro, const float* __restrict__ b_ro,
    float* __restrict__ out)
{
    extern __shared__ float sm[];
    char* smc = (char*)sm;
    const int tid  = threadIdx.x;
    const int wid  = tid >> 5;
    const int lane = tid & 31;
    const int g    = tid >> 7;         // sample group 0..3
    const int wg   = (tid >> 5) & 3;   // warp in group (owns rows 32wg..32wg+31)
    const int b    = blockIdx.x * NGROUPS + g;
    const int q2   = (lane & 3) * 2;
    const int rq   = lane >> 2;

    // ---- small weights to smem ----
    for (int idx = tid; idx < 96; idx += THREADS) sm[WL_OFF + idx] = W_lift[idx];
    if (tid < 32)                                 sm[BL_OFF + tid] = b_lift[tid];
    for (int idx = tid; idx < 96; idx += THREADS) sm[B1_OFF + idx] = b1[idx];
    for (int idx = tid; idx < 96; idx += THREADS) sm[B2_OFF + idx] = b2[idx];
    if (tid < 32)                                 sm[WRO_OFF + tid] = W_ro[tid];

    // ---- stage W1/W2 as B-fragment-packed bf16 hi/lo (6 sections x 4096B) ----
    for (int s = tid; s < 1536; s += THREADS) {
        int ln = s & 31, kc = (s >> 5) & 1, nt = (s >> 6) & 3, w = (s >> 8) & 1, l = s >> 9;
        const float* W = (w ? W2 : W1) + l * 1024;
        int n = nt * 8 + (ln >> 2), k0 = kc * 16 + (ln & 3) * 2;
        uint32_t hi0, lo0, hi1, lo1;
        split2(W[k0 * 32 + n],        W[(k0 + 1) * 32 + n], hi0, lo0);
        split2(W[(k0 + 8) * 32 + n],  W[(k0 + 9) * 32 + n], hi1, lo1);
        char* base = smc + WB_OFF * 4 + (l * 2 + w) * 4096 + ((nt * 2 + kc) * 32 + ln) * 8;
        *(uint2*)base          = make_uint2(hi0, hi1);
        *(uint2*)(base + 2048) = make_uint2(lo0, lo1);
    }

    // ---- stage adj as A-fragment-packed bf16 hi/lo ----
    for (int s = tid; s < 2048; s += THREADS) {
        int mt = s >> 8, kc = (s >> 5) & 7, ln = s & 31;
        int r = mt * 16 + (ln >> 2);
        int k = kc * 16 + (ln & 3) * 2;
        const float* a0 = adj + r * 128 + k;
        const float* a1 = a0 + 8 * 128;
        uint32_t hi[4], lo[4];
        split2(a0[0], a0[1], hi[0], lo[0]);
        split2(a1[0], a1[1], hi[1], lo[1]);
        split2(a0[8], a0[9], hi[2], lo[2]);
        split2(a1[8], a1[9], hi[3], lo[3]);
        *(uint4*)(smc + (AFH_OFF + s * 4) * 4) = make_uint4(hi[0], hi[1], hi[2], hi[3]);
        *(uint4*)(smc + (AFL_OFF + s * 4) * 4) = make_uint4(lo[0], lo[1], lo[2], lo[3]);
    }
    __syncthreads();

    // ---- lift directly into D-layout regs: rows 32wg+16mt+8rh+rq ----
    float h[32];
    {
        float xr[4][3];
        #pragma unroll
        for (int mt = 0; mt < 2; mt++)
            #pragma unroll
            for (int rh = 0; rh < 2; rh++) {
                int row = 32 * wg + 16 * mt + 8 * rh + rq;
                const float* xp = x + ((size_t)b * 128 + row) * 3;
                xr[mt * 2 + rh][0] = xp[0];
                xr[mt * 2 + rh][1] = xp[1];
                xr[mt * 2 + rh][2] = xp[2];
            }
        #pragma unroll
        for (int nt = 0; nt < 4; nt++) {
            int c0 = nt * 8 + q2;
            float2 w0 = *(const float2*)(sm + WL_OFF + c0);
            float2 w1 = *(const float2*)(sm + WL_OFF + 32 + c0);
            float2 w2 = *(const float2*)(sm + WL_OFF + 64 + c0);
            float2 bb = *(const float2*)(sm + BL_OFF + c0);
            #pragma unroll
            for (int mt = 0; mt < 2; mt++)
                #pragma unroll
                for (int rh = 0; rh < 2; rh++) {
                    const float* xv = xr[mt * 2 + rh];
                    int idx = (mt * 4 + nt) * 4 + rh * 2;
                    h[idx]     = fmaf(xv[0], w0.x, fmaf(xv[1], w1.x, fmaf(xv[2], w2.x, bb.x)));
                    h[idx + 1] = fmaf(xv[0], w0.y, fmaf(xv[1], w1.y, fmaf(xv[2], w2.y, bb.y)));
                }
        }
    }

    char* lb0 = smc + (LB_OFF + g * 8192) * 4;    // double buffer: 2 x [Bhi 8KB][Blo 8KB]

    for (int l = 0; l < 3; l++) {
        // ---- MLP1 (+relu) and MLP2, all register-resident ----
        mlp_step(h, smc + WB_OFF * 4 + (l * 2 + 0) * 4096, sm + B1_OFF + l * 32, lane, true);
        mlp_step(h, smc + WB_OFF * 4 + (l * 2 + 1) * 4096, sm + B2_OFF + l * 32, lane, false);

        char* lb = lb0 + (l & 1) * 16384;          // this layer's buffer

        // ---- scatter v into agg B-fragment-packed hi/lo arrays ----
        #pragma unroll
        for (int mt = 0; mt < 2; mt++)
            #pragma unroll
            for (int rh = 0; rh < 2; rh++) {
                int j = 32 * wg + 16 * mt + 8 * rh + rq;
                int joff = ((j >> 4) << 8) | (((j >> 1) & 3) << 3) |
                           (((j >> 3) & 1) << 2) | ((j & 1) << 1);
                #pragma unroll
                for (int nt = 0; nt < 4; nt++) {
                    int idx = (mt * 4 + nt) * 4 + rh * 2;
                    u16 h0 = bfh(h[idx]);
                    u16 l0 = bfh(h[idx] - bfup(h0));
                    u16 h1 = bfh(h[idx + 1]);
                    u16 l1 = bfh(h[idx + 1] - bfup(h1));
                    int off0 = (nt << 11) | (q2 << 5) | joff;
                    int off1 = (nt << 11) | ((q2 + 1) << 5) | joff;
                    *(u16*)(lb + off0)        = h0;
                    *(u16*)(lb + 8192 + off0) = l0;
                    *(u16*)(lb + off1)        = h1;
                    *(u16*)(lb + 8192 + off1) = l1;
                }
            }
        __syncthreads();   // scatter complete before agg reads (ONLY sync per layer)

        // ---- aggregation: D = Ahi@Bhi + Alo@Bhi + Ahi@Blo ----
        float d[32];
        #pragma unroll
        for (int e = 0; e < 32; e++) d[e] = 0.f;
        #pragma unroll 2
        for (int kc = 0; kc < 8; kc++) {
            uint2 bh[4];
            #pragma unroll
            for (int nt = 0; nt < 4; nt++)
                bh[nt] = *(const uint2*)(lb + (((nt * 8 + kc) * 32 + lane) << 3));
            uint4 ahh[2], all[2];
            #pragma unroll
            for (int mt = 0; mt < 2; mt++) {
                int sidx = ((((2 * wg + mt) * 8 + kc) * 32 + lane) << 4);
                ahh[mt] = *(const uint4*)(smc + AFH_OFF * 4 + sidx);
                all[mt] = *(const uint4*)(smc + AFL_OFF * 4 + sidx);
            }
            #pragma unroll
            for (int mt = 0; mt < 2; mt++)
                #pragma unroll
                for (int nt = 0; nt < 4; nt++) {
                    float* dd = d + ((mt * 4 + nt) << 2);
                    mma_bf16(dd, (const uint32_t*)&ahh[mt], (const uint32_t*)&bh[nt]);
                    mma_bf16(dd, (const uint32_t*)&all[mt], (const uint32_t*)&bh[nt]);
                }
            uint2 bl[4];
            #pragma unroll
            for (int nt = 0; nt < 4; nt++)
                bl[nt] = *(const uint2*)(lb + 8192 + (((nt * 8 + kc) * 32 + lane) << 3));
            #pragma unroll
            for (int mt = 0; mt < 2; mt++)
                #pragma unroll
                for (int nt = 0; nt < 4; nt++)
                    mma_bf16(d + ((mt * 4 + nt) << 2),
                             (const uint32_t*)&ahh[mt], (const uint32_t*)&bl[nt]);
        }
        #pragma unroll
        for (int e = 0; e < 32; e++) h[e] = d[e];
        // no trailing sync: next layer scatters into the OTHER buffer, and the
        // next sync happens only after every warp finished this layer's agg.
    }

    // ---- readout from D-layout regs ----
    float s = 0.f;
    #pragma unroll
    for (int nt = 0; nt < 4; nt++) {
        int c0 = nt * 8 + q2;
        float2 w = *(const float2*)(sm + WRO_OFF + c0);
        #pragma unroll
        for (int mt = 0; mt < 2; mt++) {
            const float* dd = h + (mt * 4 + nt) * 4;
            s = fmaf(dd[0] + dd[2], w.x, s);
            s = fmaf(dd[1] + dd[3], w.y, s);
        }
    }
    #pragma unroll
    for (int o = 16; o > 0; o >>= 1) s += __shfl_xor_sync(0xffffffffu, s, o);
    if (lane == 0) sm[RED_OFF + wid] = s;
    __syncthreads();
    if ((tid & 127) == 0) {
        float tot = sm[RED_OFF + 4 * g] + sm[RED_OFF + 4 * g + 1] +
                    sm[RED_OFF + 4 * g + 2] + sm[RED_OFF + 4 * g + 3];
        out[b] = fmaf(tot, 1.f / 128.f, b_ro[0]);
    }
}

extern "C" void kernel_launch(void* const* d_in, const int* in_sizes, int n_in,
                              void* d_out, int out_size)
{
    const float* x      = (const float*)d_in[0];
    const float* adj    = (const float*)d_in[1];
    const float* W_lift = (const float*)d_in[2];
    const float* b_lift = (const float*)d_in[3];
    const float* W1     = (const float*)d_in[4];
    const float* b1     = (const float*)d_in[5];
    const float* W2     = (const float*)d_in[6];
    const float* b2     = (const float*)d_in[7];
    const float* W_ro   = (const float*)d_in[8];
    const float* b_ro   = (const float*)d_in[9];
    float* out = (float*)d_out;

    const size_t smem_bytes = SMEM_FLOATS * sizeof(float);
    cudaFuncSetAttribute(gnn_mma3_kernel,
                         cudaFuncAttributeMaxDynamicSharedMemorySize,
                         (int)smem_bytes);

    gnn_mma3_kernel<<<BATCH / NGROUPS, THREADS, smem_bytes>>>(
        x, adj, W_lift, b_lift, W1, b1, W2, b2, W_ro, b_ro, out);
}